// round 7
// baseline (speedup 1.0000x reference)
#include <cuda_runtime.h>
#include <cuda_bf16.h>
#include <cstdint>

// ---------------------------------------------------------------------------
// FixedHiddenMLP -> scalar: scale_to_le1( sum relu( X@M + c ) )
//   M[k][m] = sum_j W[j,k]*R[j,m],  c[m] = sum_j b[j]*R[j,m] + 1
//
// Round 7: transposed (k-major) x tile in smem.
//  - 4 rows/thread, k-outer / m-inner-full: acc[4][10] f32x2 (80 regs),
//    x per k = ONE conflict-free LDS.128 (its 4 consecutive rows).
//  - launch_bounds(128,1): let ptxas use >128 regs instead of spilling
//    (round 6 hit the 128-reg wall with a 160-reg x array).
//  - stage: coalesced LDG.128 + STS.32 transpose (row stride 516 words).
// ---------------------------------------------------------------------------

#define D    20
#define NT   128                  // threads per block
#define NB   1184                 // 148 SMs * 8
#define TP   512                  // rows per tile = NT * 4
#define TPS  516                  // floats per k-row in xs_t (pad: 516%32=4)

__device__ double       g_part[NB];
__device__ unsigned int g_count;      // zero-init; last block resets

typedef unsigned long long u64;

// --- f32x2 helpers ---------------------------------------------------------
__device__ __forceinline__ u64 dup2(float v) {
    u64 r;
    asm("mov.b64 %0, {%1, %1};" : "=l"(r) : "f"(v));
    return r;
}
__device__ __forceinline__ void unpack2(u64 v, float& lo, float& hi) {
    asm("mov.b64 {%0, %1}, %2;" : "=f"(lo), "=f"(hi) : "l"(v));
}
__device__ __forceinline__ u64 fma2(u64 a, u64 b, u64 c) {
    u64 d;
    asm("fma.rn.f32x2 %0, %1, %2, %3;" : "=l"(d) : "l"(a), "l"(b), "l"(c));
    return d;
}
__device__ __forceinline__ u64 add2(u64 a, u64 b) {
    u64 d;
    asm("add.rn.f32x2 %0, %1, %2;" : "=l"(d) : "l"(a), "l"(b));
    return d;
}

__global__ void __launch_bounds__(NT, 1)
fused_mlp_kernel(const float* __restrict__ X,
                 const float* __restrict__ W,
                 const float* __restrict__ bias,
                 const float* __restrict__ R,
                 float* __restrict__ out,
                 long long nrows)
{
    __shared__ __align__(16) u64   sM2[D * 10];    // (M[k][2p], M[k][2p+1])
    __shared__ __align__(16) u64   sC2[10];        // (c[2p], c[2p+1])
    __shared__ __align__(16) float xs_t[D * TPS];  // k-major x tile (41280 B)
    __shared__ double sred[NT];

    const int tid = threadIdx.x;

    // --- fold the two tiny matmuls into sM2 / sC2 --------------------------
    float* sMf = (float*)sM2;           // float view: sMf[k*20+m]
    for (int idx = tid; idx < D * D; idx += NT) {
        const int k = idx / D, m = idx % D;
        float acc = 0.f;
        #pragma unroll
        for (int j = 0; j < D; ++j)
            acc += W[j * D + k] * R[j * D + m];
        sMf[k * D + m] = acc;
    }
    if (tid < D) {
        float acc = 1.f;
        #pragma unroll
        for (int j = 0; j < D; ++j)
            acc += bias[j] * R[j * D + tid];
        ((float*)sC2)[tid] = acc;
    }

    const long long nrows_main = nrows & ~3LL;
    const long long ntiles = (nrows_main + TP - 1) / TP;
    double dacc = 0.0;

    for (long long t = blockIdx.x; t < ntiles; t += gridDim.x) {
        const long long row0 = t * TP;
        const int nr  = (int)((nrows_main - row0) < TP ? (nrows_main - row0) : TP);
        const int nf4 = nr * 5;                       // float4 granules

        __syncthreads();    // xs_t reuse guard (covers fold on first iter)

        // ---- stage + transpose: coalesced LDG.128, STS.32 scatter ---------
        const float4* __restrict__ src = (const float4*)(X + row0 * D);
        for (int g = tid; g < nf4; g += NT) {
            const int row = g / 5;
            const int c   = g - row * 5;              // float4 piece: k=4c..4c+3
            const float4 v = src[g];
            float* col = &xs_t[(4 * c) * TPS + row];
            col[0 * TPS] = v.x;
            col[1 * TPS] = v.y;
            col[2 * TPS] = v.z;
            col[3 * TPS] = v.w;
        }
        __syncthreads();

        // ---- compute: 4 consecutive rows per thread ------------------------
        if (4 * tid < nr) {
            u64 acc[4][10];
            #pragma unroll
            for (int r = 0; r < 4; ++r)
                #pragma unroll
                for (int p = 0; p < 10; ++p) acc[r][p] = 0ULL;

            #pragma unroll
            for (int k = 0; k < D; ++k) {
                // one conflict-free LDS.128: this thread's 4 rows at column k
                const float4 xq = *(const float4*)&xs_t[k * TPS + 4 * tid];
                const u64 d0 = dup2(xq.x);
                const u64 d1 = dup2(xq.y);
                const u64 d2 = dup2(xq.z);
                const u64 d3 = dup2(xq.w);
                const ulonglong2* mp = (const ulonglong2*)(sM2 + k * 10);
                #pragma unroll
                for (int h = 0; h < 5; ++h) {
                    const ulonglong2 mv = mp[h];      // broadcast LDS.128
                    acc[0][2*h+0] = fma2(d0, mv.x, acc[0][2*h+0]);
                    acc[0][2*h+1] = fma2(d0, mv.y, acc[0][2*h+1]);
                    acc[1][2*h+0] = fma2(d1, mv.x, acc[1][2*h+0]);
                    acc[1][2*h+1] = fma2(d1, mv.y, acc[1][2*h+1]);
                    acc[2][2*h+0] = fma2(d2, mv.x, acc[2][2*h+0]);
                    acc[2][2*h+1] = fma2(d2, mv.y, acc[2][2*h+1]);
                    acc[3][2*h+0] = fma2(d3, mv.x, acc[3][2*h+0]);
                    acc[3][2*h+1] = fma2(d3, mv.y, acc[3][2*h+1]);
                }
            }

            // ---- epilogue: +c, relu, sum (halves are free register views) -
            float rs0 = 0.f, rs1 = 0.f, rs2 = 0.f, rs3 = 0.f;
            #pragma unroll
            for (int p = 0; p < 10; ++p) {
                const u64 cp = sC2[p];
                {
                    float lo, hi; unpack2(add2(acc[0][p], cp), lo, hi);
                    rs0 += fmaxf(lo, 0.f) + fmaxf(hi, 0.f);
                }
                {
                    float lo, hi; unpack2(add2(acc[1][p], cp), lo, hi);
                    rs1 += fmaxf(lo, 0.f) + fmaxf(hi, 0.f);
                }
                {
                    float lo, hi; unpack2(add2(acc[2][p], cp), lo, hi);
                    rs2 += fmaxf(lo, 0.f) + fmaxf(hi, 0.f);
                }
                {
                    float lo, hi; unpack2(add2(acc[3][p], cp), lo, hi);
                    rs3 += fmaxf(lo, 0.f) + fmaxf(hi, 0.f);
                }
            }
            dacc += (double)((rs0 + rs1) + (rs2 + rs3));
        }
    }

    // --- generic tail rows (nrows % 4; zero for this dataset) --------------
    if (blockIdx.x == 0 && tid == 0) {
        float* sMf2 = (float*)sM2;
        for (long long r = nrows_main; r < nrows; ++r) {
            const float* xr = X + r * D;
            float rs = 0.f;
            for (int m = 0; m < D; ++m) {
                float acc = ((float*)sC2)[m];
                for (int k = 0; k < D; ++k) acc += xr[k] * sMf2[k * D + m];
                rs += fmaxf(acc, 0.f);
            }
            dacc += (double)rs;
        }
    }

    // --- block reduce -------------------------------------------------------
    __syncthreads();
    sred[tid] = dacc;
    __syncthreads();
    #pragma unroll
    for (int s = NT / 2; s > 0; s >>= 1) {
        if (tid < s) sred[tid] += sred[tid + s];
        __syncthreads();
    }
    if (tid == 0) g_part[blockIdx.x] = sred[0];

    // --- last-block global reduce + halving loop ---------------------------
    __shared__ bool is_last;
    if (tid == 0) {
        __threadfence();
        is_last = (atomicAdd(&g_count, 1u) == (unsigned)(gridDim.x - 1));
    }
    __syncthreads();
    if (is_last) {
        double acc = 0.0;
        for (int i = tid; i < NB; i += NT) acc += g_part[i];
        sred[tid] = acc;
        __syncthreads();
        #pragma unroll
        for (int s = NT / 2; s > 0; s >>= 1) {
            if (tid < s) sred[tid] += sred[tid + s];
            __syncthreads();
        }
        if (tid == 0) {
            float v = (float)sred[0];
            int n = 0;
            while (v > 1.0f && n < 4096) { v *= 0.5f; ++n; }  // exact /2
            out[0] = v;
            g_count = 0;     // reset for next graph replay
        }
    }
}

extern "C" void kernel_launch(void* const* d_in, const int* in_sizes, int n_in,
                              void* d_out, int out_size)
{
    const float* X = (const float*)d_in[0];
    const float* W = (const float*)d_in[1];
    const float* b = (const float*)d_in[2];
    const float* R = (const float*)d_in[3];
    float* out = (float*)d_out;

    const long long nrows = (long long)in_sizes[0] / D;

    fused_mlp_kernel<<<NB, NT>>>(X, W, b, R, out, nrows);
}

// round 8
// speedup vs baseline: 1.1770x; 1.1770x over previous
#include <cuda_runtime.h>
#include <cuda_bf16.h>
#include <cstdint>

// ---------------------------------------------------------------------------
// FixedHiddenMLP -> scalar: scale_to_le1( sum relu( X@M + c ) )
//   M[k][m] = sum_j W[j,k]*R[j,m],  c[m] = sum_j b[j]*R[j,m] + 1
//
// Round 8: double-buffered cp.async pipeline (kill the fill/compute bubble
// diagnosed from rounds 5-7: no pipe above 50% => serialization, not ceiling).
//  - NT=128, tile = 128 row-pairs, 2 rows/thread (acc 40 regs, ~105 total).
//  - pair slot = 44 floats (conflict-free LDS.128: 12*t mod 32 covers all
//    banks across the 8 lanes of each phase).
//  - prefetch depth 2: wait_group 1 -> sync -> compute -> sync -> refill.
// ---------------------------------------------------------------------------

#define D     20
#define NT    128                 // threads per block
#define NB    1184                // 148 SMs * 8
#define TPP   128                 // row-pairs per tile (== NT)
#define PADF  44                  // floats per pair slot (11 x 16B granules)

__device__ double       g_part[NB];
__device__ unsigned int g_count;      // zero-init; last block resets

typedef unsigned long long u64;

// --- f32x2 helpers ---------------------------------------------------------
__device__ __forceinline__ u64 dup2(float v) {
    u64 r;
    asm("mov.b64 %0, {%1, %1};" : "=l"(r) : "f"(v));
    return r;
}
__device__ __forceinline__ void unpack2(u64 v, float& lo, float& hi) {
    asm("mov.b64 {%0, %1}, %2;" : "=f"(lo), "=f"(hi) : "l"(v));
}
__device__ __forceinline__ u64 fma2(u64 a, u64 b, u64 c) {
    u64 d;
    asm("fma.rn.f32x2 %0, %1, %2, %3;" : "=l"(d) : "l"(a), "l"(b), "l"(c));
    return d;
}
__device__ __forceinline__ u64 add2(u64 a, u64 b) {
    u64 d;
    asm("add.rn.f32x2 %0, %1, %2;" : "=l"(d) : "l"(a), "l"(b));
    return d;
}

// --- cp.async helpers ------------------------------------------------------
__device__ __forceinline__ uint32_t smem_u32(const void* p) {
    uint32_t a;
    asm("{ .reg .u64 t; cvta.to.shared.u64 t, %1; cvt.u32.u64 %0, t; }"
        : "=r"(a) : "l"(p));
    return a;
}
__device__ __forceinline__ void cpa16(uint32_t dst, const void* src) {
    asm volatile("cp.async.ca.shared.global [%0], [%1], 16;" :: "r"(dst), "l"(src));
}
__device__ __forceinline__ void cpa_commit() {
    asm volatile("cp.async.commit_group;");
}
__device__ __forceinline__ void cpa_wait1() {
    asm volatile("cp.async.wait_group 1;" ::: "memory");
}

__global__ void __launch_bounds__(NT)
fused_mlp_kernel(const float* __restrict__ X,
                 const float* __restrict__ W,
                 const float* __restrict__ bias,
                 const float* __restrict__ R,
                 float* __restrict__ out,
                 long long nrows)
{
    __shared__ __align__(16) u64   sM2[D * 10];        // (M[k][2p],M[k][2p+1])
    __shared__ __align__(16) u64   sC2[10];            // (c[2p], c[2p+1])
    __shared__ __align__(16) float xs[2][TPP * PADF];  // double buffer, 45KB
    __shared__ double sred[NT];

    const int tid = threadIdx.x;

    // --- fold the two tiny matmuls -----------------------------------------
    float* sMf = (float*)sM2;
    for (int idx = tid; idx < D * D; idx += NT) {
        const int k = idx / D, m = idx % D;
        float acc = 0.f;
        #pragma unroll
        for (int j = 0; j < D; ++j)
            acc += W[j * D + k] * R[j * D + m];
        sMf[k * D + m] = acc;
    }
    if (tid < D) {
        float acc = 1.f;
        #pragma unroll
        for (int j = 0; j < D; ++j)
            acc += bias[j] * R[j * D + tid];
        ((float*)sC2)[tid] = acc;
    }
    __syncthreads();

    const long long npairs = nrows >> 1;
    const long long ntiles = (npairs + TPP - 1) / TPP;
    const uint32_t  xb0 = smem_u32(&xs[0][0]);
    const uint32_t  xb1 = smem_u32(&xs[1][0]);

    // tile filler: granule g covers pair pr=g/10, piece pc=g%10
    auto fill = [&](uint32_t xbase, long long t) {
        if (t < ntiles) {
            const long long p0 = t * TPP;
            const int ptile = (int)((npairs - p0) < TPP ? (npairs - p0) : TPP);
            const char* src = (const char*)(X + p0 * (2 * D));
            const int gran = ptile * 10;
            for (int g = tid; g < gran; g += NT) {
                const int pr = g / 10;
                const int pc = g - pr * 10;
                cpa16(xbase + (pr * PADF + pc * 4) * 4, src + (size_t)g * 16);
            }
        }
        cpa_commit();   // empty group when t >= ntiles (legal, completes fast)
    };

    double dacc = 0.0;
    const long long t0 = blockIdx.x;

    // --- prologue: prefetch two tiles --------------------------------------
    fill(xb0, t0);
    fill(xb1, t0 + NB);

    int buf = 0;
    for (long long t = t0; t < ntiles; t += NB) {
        cpa_wait1();          // group for `buf` complete (<=1 newer pending)
        __syncthreads();      // make fills visible to all threads

        // ---- compute: this thread's pair (2 rows) -------------------------
        const long long p0 = t * TPP;
        const int ptile = (int)((npairs - p0) < TPP ? (npairs - p0) : TPP);
        if (tid < ptile) {
            const float* gp = &xs[buf][tid * PADF];
            float4 xa[10];
            #pragma unroll
            for (int h = 0; h < 10; ++h)
                xa[h] = *(const float4*)(gp + h * 4);   // conflict-free

            u64 acc0[10], acc1[10];
            #pragma unroll
            for (int p = 0; p < 10; ++p) { acc0[p] = 0ULL; acc1[p] = 0ULL; }

            const float* x0 = (const float*)&xa[0];     // row 0: 20 floats
            const float* x1 = (const float*)&xa[5];     // row 1: 20 floats

            #pragma unroll
            for (int k = 0; k < D; ++k) {
                const u64 d0 = dup2(x0[k]);
                const u64 d1 = dup2(x1[k]);
                const ulonglong2* mp = (const ulonglong2*)(sM2 + k * 10);
                #pragma unroll
                for (int h = 0; h < 5; ++h) {
                    const ulonglong2 mv = mp[h];        // broadcast LDS.128
                    acc0[2*h+0] = fma2(d0, mv.x, acc0[2*h+0]);
                    acc0[2*h+1] = fma2(d0, mv.y, acc0[2*h+1]);
                    acc1[2*h+0] = fma2(d1, mv.x, acc1[2*h+0]);
                    acc1[2*h+1] = fma2(d1, mv.y, acc1[2*h+1]);
                }
            }

            float rs0 = 0.f, rs1 = 0.f;
            #pragma unroll
            for (int p = 0; p < 10; ++p) {
                const u64 cp = sC2[p];
                float lo, hi;
                unpack2(add2(acc0[p], cp), lo, hi);
                rs0 += fmaxf(lo, 0.f) + fmaxf(hi, 0.f);
                unpack2(add2(acc1[p], cp), lo, hi);
                rs1 += fmaxf(lo, 0.f) + fmaxf(hi, 0.f);
            }
            dacc += (double)(rs0 + rs1);
        }

        __syncthreads();      // all compute reads done before refilling buf
        fill(buf ? xb1 : xb0, t + 2 * NB);
        buf ^= 1;
    }

    // --- odd-row tail -------------------------------------------------------
    if ((nrows & 1) && blockIdx.x == 0 && tid == 0) {
        const float* xr = X + (nrows - 1) * D;
        float rs = 0.f;
        for (int m = 0; m < D; ++m) {
            float acc = ((float*)sC2)[m];
            for (int k = 0; k < D; ++k) acc += xr[k] * sMf[k * D + m];
            rs += fmaxf(acc, 0.f);
        }
        dacc += (double)rs;
    }

    // --- block reduce -------------------------------------------------------
    __syncthreads();
    sred[tid] = dacc;
    __syncthreads();
    #pragma unroll
    for (int s = NT / 2; s > 0; s >>= 1) {
        if (tid < s) sred[tid] += sred[tid + s];
        __syncthreads();
    }
    if (tid == 0) g_part[blockIdx.x] = sred[0];

    // --- last-block global reduce + halving loop ---------------------------
    __shared__ bool is_last;
    if (tid == 0) {
        __threadfence();
        is_last = (atomicAdd(&g_count, 1u) == (unsigned)(gridDim.x - 1));
    }
    __syncthreads();
    if (is_last) {
        double acc = 0.0;
        for (int i = tid; i < NB; i += NT) acc += g_part[i];
        sred[tid] = acc;
        __syncthreads();
        #pragma unroll
        for (int s = NT / 2; s > 0; s >>= 1) {
            if (tid < s) sred[tid] += sred[tid + s];
            __syncthreads();
        }
        if (tid == 0) {
            float v = (float)sred[0];
            int n = 0;
            while (v > 1.0f && n < 4096) { v *= 0.5f; ++n; }  // exact /2
            out[0] = v;
            g_count = 0;     // reset for next graph replay
        }
    }
}

extern "C" void kernel_launch(void* const* d_in, const int* in_sizes, int n_in,
                              void* d_out, int out_size)
{
    const float* X = (const float*)d_in[0];
    const float* W = (const float*)d_in[1];
    const float* b = (const float*)d_in[2];
    const float* R = (const float*)d_in[3];
    float* out = (float*)d_out;

    const long long nrows = (long long)in_sizes[0] / D;

    fused_mlp_kernel<<<NB, NT>>>(X, W, b, R, out, nrows);
}

// round 11
// speedup vs baseline: 1.4301x; 1.2151x over previous
#include <cuda_runtime.h>
#include <cuda_bf16.h>
#include <cstdint>

// ---------------------------------------------------------------------------
// FixedHiddenMLP -> scalar: scale_to_le1( sum relu( X@M + c ) )
//   M[k][m] = sum_j W[j,k]*R[j,m],  c[m] = sum_j b[j]*R[j,m] + 1
//
// Round 10: TMA-bulk staging + 4 rows/thread + unpadded strided-row tile.
//  - cp.async.bulk (sm_90 base ISA: compiles at target sm_103) stages 40KB
//    tiles with ONE instruction -> zero per-warp LDGSTS cost.
//  - rows tid, tid+128, tid+256, tid+384: lane stride 80B = 20 words mod 32
//    -> LDS.128 conflict-free WITHOUT padding (so the tile stays contiguous).
//  - 4-row M reuse: 100 broadcast M-LDS per 128 rows (was 200).
//  - partial tiles zero-filled; overcount subtracted exactly in finalizer.
// ---------------------------------------------------------------------------

#define D    20
#define NT   128
#define NB   592                  // 148 SMs * 4 CTAs... resident: 2/SM * 296
#define TRW  512                  // rows per tile
#define TILE_FLOATS (TRW * D)     // 10240 floats = 40960 B

// dynamic smem layout (bytes)
#define OFF_XS0   0u
#define OFF_XS1   40960u
#define OFF_SM2   81920u          // 200 u64 = 1600
#define OFF_SC2   83520u          // 10 u64 = 80
#define OFF_MBAR  83600u          // 2 x 8
#define OFF_SRED  83616u          // 128 x 8 = 1024
#define SMEM_TOTAL 84640

typedef unsigned long long u64;

__device__ double       g_part[NB];
__device__ unsigned int g_count;

// --- f32x2 helpers ---------------------------------------------------------
__device__ __forceinline__ u64 dup2(float v) {
    u64 r; asm("mov.b64 %0, {%1, %1};" : "=l"(r) : "f"(v)); return r;
}
__device__ __forceinline__ u64 pack2(float lo, float hi) {
    u64 r; asm("mov.b64 %0, {%1, %2};" : "=l"(r) : "f"(lo), "f"(hi)); return r;
}
__device__ __forceinline__ void unpack2(u64 v, float& lo, float& hi) {
    asm("mov.b64 {%0, %1}, %2;" : "=f"(lo), "=f"(hi) : "l"(v));
}
__device__ __forceinline__ u64 fma2(u64 a, u64 b, u64 c) {
    u64 d; asm("fma.rn.f32x2 %0, %1, %2, %3;" : "=l"(d) : "l"(a), "l"(b), "l"(c));
    return d;
}
__device__ __forceinline__ u64 add2(u64 a, u64 b) {
    u64 d; asm("add.rn.f32x2 %0, %1, %2;" : "=l"(d) : "l"(a), "l"(b));
    return d;
}

// --- smem addr / TMA-bulk / mbarrier helpers -------------------------------
__device__ __forceinline__ uint32_t smem_u32(const void* p) {
    uint32_t a;
    asm("{ .reg .u64 t; cvta.to.shared.u64 t, %1; cvt.u32.u64 %0, t; }"
        : "=r"(a) : "l"(p));
    return a;
}
__device__ __forceinline__ void mbar_init(uint32_t a, uint32_t cnt) {
    asm volatile("mbarrier.init.shared.b64 [%0], %1;" :: "r"(a), "r"(cnt) : "memory");
}
__device__ __forceinline__ void mbar_expect_tx(uint32_t a, uint32_t bytes) {
    asm volatile("mbarrier.arrive.expect_tx.shared.b64 _, [%0], %1;"
                 :: "r"(a), "r"(bytes) : "memory");
}
__device__ __forceinline__ void bulk_g2s(uint32_t dst, const void* src,
                                         uint32_t bytes, uint32_t mbar) {
    asm volatile(
        "cp.async.bulk.shared::cluster.global.mbarrier::complete_tx::bytes "
        "[%0], [%1], %2, [%3];"
        :: "r"(dst), "l"(src), "r"(bytes), "r"(mbar) : "memory");
}
__device__ __forceinline__ void mbar_wait(uint32_t a, uint32_t par) {
    uint32_t done;
    asm volatile("{\n\t.reg .pred p;\n\t"
        "mbarrier.try_wait.parity.acquire.cta.shared::cta.b64 p, [%1], %2;\n\t"
        "selp.b32 %0, 1, 0, p;\n\t}" : "=r"(done) : "r"(a), "r"(par) : "memory");
    if (!done) {
        asm volatile("{\n\t.reg .pred P1;\n\tWL_%=:\n\t"
            "mbarrier.try_wait.parity.acquire.cta.shared::cta.b64 P1, [%0], %1, 0x989680;\n\t"
            "@P1 bra.uni WD_%=;\n\tbra.uni WL_%=;\n\tWD_%=:\n\t}"
            :: "r"(a), "r"(par) : "memory");
    }
}

__global__ void __launch_bounds__(NT, 1)
fused_mlp_bulk(const float* __restrict__ X,
               const float* __restrict__ W,
               const float* __restrict__ bias,
               const float* __restrict__ R,
               float* __restrict__ out,
               long long nrows)
{
    extern __shared__ __align__(1024) unsigned char smem[];
    const uint32_t sb  = smem_u32(smem);
    const int      tid = threadIdx.x;

    u64*   sM2u = (u64*)(smem + OFF_SM2);     // (M[k][2p], M[k][2p+1])
    u64*   sC2u = (u64*)(smem + OFF_SC2);
    float* sMf  = (float*)sM2u;
    float* sCf  = (float*)sC2u;
    double* sred = (double*)(smem + OFF_SRED);

    // --- init mbarriers + fold the tiny matmuls ----------------------------
    if (tid == 0) {
        mbar_init(sb + OFF_MBAR,     1);
        mbar_init(sb + OFF_MBAR + 8, 1);
    }
    for (int idx = tid; idx < D * D; idx += NT) {
        const int k = idx / D, m = idx % D;
        float acc = 0.f;
        #pragma unroll
        for (int j = 0; j < D; ++j)
            acc += W[j * D + k] * R[j * D + m];
        sMf[k * D + m] = acc;
    }
    if (tid < D) {
        float acc = 1.f;
        #pragma unroll
        for (int j = 0; j < D; ++j)
            acc += bias[j] * R[j * D + tid];
        sCf[tid] = acc;
    }
    __syncthreads();

    const long long ntiles = (nrows + TRW - 1) / TRW;

    // tile filler: zero-pad partial tiles, one bulk copy, tx on buffer's mbar
    auto fill = [&](int b, long long t) {
        if (t >= ntiles) return;
        const long long row0 = t * TRW;
        const int nr = (int)((nrows - row0) < TRW ? (nrows - row0) : TRW);
        float* dst = (float*)(smem + (b ? OFF_XS1 : OFF_XS0));
        if (nr < TRW) {
            const int zwords = (TRW - nr) * D;
            for (int i = tid; i < zwords; i += NT) dst[nr * D + i] = 0.f;
        }
        if (tid == 0) {
            const uint32_t bytes = (uint32_t)nr * (D * 4);
            const uint32_t mb = sb + OFF_MBAR + (b ? 8 : 0);
            mbar_expect_tx(mb, bytes);
            bulk_g2s(sb + (b ? OFF_XS1 : OFF_XS0), X + row0 * D, bytes, mb);
        }
    };

    double dacc = 0.0;
    int ph0 = 0, ph1 = 0;
    const long long t0 = blockIdx.x;

    fill(0, t0);
    fill(1, t0 + NB);

    int buf = 0;
    for (long long t = t0; t < ntiles; t += NB) {
        // wait for this buffer's tile
        mbar_wait(sb + OFF_MBAR + (buf ? 8 : 0), (uint32_t)(buf ? ph1 : ph0));
        if (buf) ph1 ^= 1; else ph0 ^= 1;

        const float* bp = (const float*)(smem + (buf ? OFF_XS1 : OFF_XS0));

        // init accumulators from folded bias (saves 40 add2 on fma pipe)
        u64 a0[10], a1[10], a2[10], a3[10];
        #pragma unroll
        for (int p = 0; p < 10; ++p) {
            const u64 cp = sC2u[p];
            a0[p] = cp; a1[p] = cp; a2[p] = cp; a3[p] = cp;
        }

        #pragma unroll
        for (int q = 0; q < 5; ++q) {
            // 4 conflict-free LDS.128 (lane stride 20 words tiles all banks)
            const float4 x0 = *(const float4*)(bp + (tid +   0) * D + q * 4);
            const float4 x1 = *(const float4*)(bp + (tid + 128) * D + q * 4);
            const float4 x2 = *(const float4*)(bp + (tid + 256) * D + q * 4);
            const float4 x3 = *(const float4*)(bp + (tid + 384) * D + q * 4);
            const float* f0 = (const float*)&x0;
            const float* f1 = (const float*)&x1;
            const float* f2 = (const float*)&x2;
            const float* f3 = (const float*)&x3;
            #pragma unroll
            for (int kk = 0; kk < 4; ++kk) {
                const int k = 4 * q + kk;
                const u64 d0 = dup2(f0[kk]);
                const u64 d1 = dup2(f1[kk]);
                const u64 d2 = dup2(f2[kk]);
                const u64 d3 = dup2(f3[kk]);
                const ulonglong2* mp = (const ulonglong2*)(sM2u + k * 10);
                #pragma unroll
                for (int h = 0; h < 5; ++h) {
                    const ulonglong2 mv = mp[h];    // broadcast LDS.128
                    a0[2*h+0] = fma2(d0, mv.x, a0[2*h+0]);
                    a0[2*h+1] = fma2(d0, mv.y, a0[2*h+1]);
                    a1[2*h+0] = fma2(d1, mv.x, a1[2*h+0]);
                    a1[2*h+1] = fma2(d1, mv.y, a1[2*h+1]);
                    a2[2*h+0] = fma2(d2, mv.x, a2[2*h+0]);
                    a2[2*h+1] = fma2(d2, mv.y, a2[2*h+1]);
                    a3[2*h+0] = fma2(d3, mv.x, a3[2*h+0]);
                    a3[2*h+1] = fma2(d3, mv.y, a3[2*h+1]);
                }
            }
        }

        // epilogue: relu + sum (relu on alu pipe, pair-sums on fma)
        u64 r0 = 0ULL, r1 = 0ULL, r2 = 0ULL, r3 = 0ULL;
        #pragma unroll
        for (int p = 0; p < 10; ++p) {
            float lo, hi;
            unpack2(a0[p], lo, hi);
            r0 = add2(r0, pack2(fmaxf(lo, 0.f), fmaxf(hi, 0.f)));
            unpack2(a1[p], lo, hi);
            r1 = add2(r1, pack2(fmaxf(lo, 0.f), fmaxf(hi, 0.f)));
            unpack2(a2[p], lo, hi);
            r2 = add2(r2, pack2(fmaxf(lo, 0.f), fmaxf(hi, 0.f)));
            unpack2(a3[p], lo, hi);
            r3 = add2(r3, pack2(fmaxf(lo, 0.f), fmaxf(hi, 0.f)));
        }
        const u64 rr = add2(add2(r0, r1), add2(r2, r3));
        float slo, shi;
        unpack2(rr, slo, shi);
        dacc += (double)(slo + shi);

        __syncthreads();          // all reads of buf done before refill
        fill(buf, t + 2 * NB);
        buf ^= 1;
    }

    // --- block reduce -------------------------------------------------------
    __syncthreads();
    sred[tid] = dacc;
    __syncthreads();
    #pragma unroll
    for (int s = NT / 2; s > 0; s >>= 1) {
        if (tid < s) sred[tid] += sred[tid + s];
        __syncthreads();
    }
    if (tid == 0) g_part[blockIdx.x] = sred[0];

    // --- last-block: global reduce, fake-row correction, halving loop ------
    __shared__ bool is_last;
    if (tid == 0) {
        __threadfence();
        is_last = (atomicAdd(&g_count, 1u) == (unsigned)(gridDim.x - 1));
    }
    __syncthreads();
    if (is_last) {
        double acc = 0.0;
        for (int i = tid; i < NB; i += NT) acc += g_part[i];
        sred[tid] = acc;
        __syncthreads();
        #pragma unroll
        for (int s = NT / 2; s > 0; s >>= 1) {
            if (tid < s) sred[tid] += sred[tid + s];
            __syncthreads();
        }
        if (tid == 0) {
            // zero-padded fake rows each contributed sum_m relu(c[m])
            const long long fake = ntiles * TRW - nrows;
            float rcs = 0.f;
            for (int m = 0; m < D; ++m) rcs += fmaxf(sCf[m], 0.f);
            double total = sred[0] - (double)fake * (double)rcs;

            float v = (float)total;
            int n = 0;
            while (v > 1.0f && n < 4096) { v *= 0.5f; ++n; }   // exact /2
            out[0] = v;
            g_count = 0;         // reset for next graph replay
        }
    }
}

extern "C" void kernel_launch(void* const* d_in, const int* in_sizes, int n_in,
                              void* d_out, int out_size)
{
    const float* X = (const float*)d_in[0];
    const float* W = (const float*)d_in[1];
    const float* b = (const float*)d_in[2];
    const float* R = (const float*)d_in[3];
    float* out = (float*)d_out;

    const long long nrows = (long long)in_sizes[0] / D;

    cudaFuncSetAttribute(fused_mlp_bulk,
                         cudaFuncAttributeMaxDynamicSharedMemorySize,
                         SMEM_TOTAL);
    fused_mlp_bulk<<<NB, NT, SMEM_TOTAL>>>(X, W, b, R, out, nrows);
}

// round 12
// speedup vs baseline: 1.4933x; 1.0442x over previous
#include <cuda_runtime.h>
#include <cuda_bf16.h>
#include <cstdint>

// ---------------------------------------------------------------------------
// FixedHiddenMLP -> scalar: scale_to_le1( sum relu( X@M + c ) )
//   M[k][m] = sum_j W[j,k]*R[j,m],  c[m] = sum_j b[j]*R[j,m] + 1
//
// Round 11: occupancy doubling (round-10 ncu: all pipes <50%, occ 11.3%).
//  - TRW=256 rows/tile, 2 rows/thread -> smem 43.7KB/CTA -> 4 CTAs/SM
//    (16 warps/SM, was 8). regs ~95 (acc array halved) -> not reg-capped.
//  - TMA bulk staging + unpadded strided-row tile (conflict-free LDS.128,
//    lane stride 20 words) carried over from round 10.
//  - partial tiles zero-filled; overcount subtracted exactly in finalizer.
// ---------------------------------------------------------------------------

#define D    20
#define NT   128
#define NB   592                  // 148 SMs * 4 resident CTAs
#define TRW  256                  // rows per tile = NT * 2

// dynamic smem layout (bytes)
#define OFF_XS0    0u
#define OFF_XS1    20480u
#define OFF_SM2    40960u         // 200 u64 = 1600
#define OFF_SC2    42560u         // 10 u64 = 80
#define OFF_MBAR   42640u         // 2 x 8
#define OFF_SRED   42656u         // 128 x 8 = 1024
#define SMEM_TOTAL 43680

typedef unsigned long long u64;

__device__ double       g_part[NB];
__device__ unsigned int g_count;

// --- f32x2 helpers ---------------------------------------------------------
__device__ __forceinline__ u64 dup2(float v) {
    u64 r; asm("mov.b64 %0, {%1, %1};" : "=l"(r) : "f"(v)); return r;
}
__device__ __forceinline__ u64 pack2(float lo, float hi) {
    u64 r; asm("mov.b64 %0, {%1, %2};" : "=l"(r) : "f"(lo), "f"(hi)); return r;
}
__device__ __forceinline__ void unpack2(u64 v, float& lo, float& hi) {
    asm("mov.b64 {%0, %1}, %2;" : "=f"(lo), "=f"(hi) : "l"(v));
}
__device__ __forceinline__ u64 fma2(u64 a, u64 b, u64 c) {
    u64 d; asm("fma.rn.f32x2 %0, %1, %2, %3;" : "=l"(d) : "l"(a), "l"(b), "l"(c));
    return d;
}
__device__ __forceinline__ u64 add2(u64 a, u64 b) {
    u64 d; asm("add.rn.f32x2 %0, %1, %2;" : "=l"(d) : "l"(a), "l"(b));
    return d;
}

// --- smem addr / TMA-bulk / mbarrier helpers -------------------------------
__device__ __forceinline__ uint32_t smem_u32(const void* p) {
    uint32_t a;
    asm("{ .reg .u64 t; cvta.to.shared.u64 t, %1; cvt.u32.u64 %0, t; }"
        : "=r"(a) : "l"(p));
    return a;
}
__device__ __forceinline__ void mbar_init(uint32_t a, uint32_t cnt) {
    asm volatile("mbarrier.init.shared.b64 [%0], %1;" :: "r"(a), "r"(cnt) : "memory");
}
__device__ __forceinline__ void mbar_expect_tx(uint32_t a, uint32_t bytes) {
    asm volatile("mbarrier.arrive.expect_tx.shared.b64 _, [%0], %1;"
                 :: "r"(a), "r"(bytes) : "memory");
}
__device__ __forceinline__ void bulk_g2s(uint32_t dst, const void* src,
                                         uint32_t bytes, uint32_t mbar) {
    asm volatile(
        "cp.async.bulk.shared::cluster.global.mbarrier::complete_tx::bytes "
        "[%0], [%1], %2, [%3];"
        :: "r"(dst), "l"(src), "r"(bytes), "r"(mbar) : "memory");
}
__device__ __forceinline__ void mbar_wait(uint32_t a, uint32_t par) {
    uint32_t done;
    asm volatile("{\n\t.reg .pred p;\n\t"
        "mbarrier.try_wait.parity.acquire.cta.shared::cta.b64 p, [%1], %2;\n\t"
        "selp.b32 %0, 1, 0, p;\n\t}" : "=r"(done) : "r"(a), "r"(par) : "memory");
    if (!done) {
        asm volatile("{\n\t.reg .pred P1;\n\tWL_%=:\n\t"
            "mbarrier.try_wait.parity.acquire.cta.shared::cta.b64 P1, [%0], %1, 0x989680;\n\t"
            "@P1 bra.uni WD_%=;\n\tbra.uni WL_%=;\n\tWD_%=:\n\t}"
            :: "r"(a), "r"(par) : "memory");
    }
}

__global__ void __launch_bounds__(NT)
fused_mlp_bulk(const float* __restrict__ X,
               const float* __restrict__ W,
               const float* __restrict__ bias,
               const float* __restrict__ R,
               float* __restrict__ out,
               long long nrows)
{
    extern __shared__ __align__(1024) unsigned char smem[];
    const uint32_t sb  = smem_u32(smem);
    const int      tid = threadIdx.x;

    u64*    sM2u = (u64*)(smem + OFF_SM2);     // (M[k][2p], M[k][2p+1])
    u64*    sC2u = (u64*)(smem + OFF_SC2);
    float*  sMf  = (float*)sM2u;
    float*  sCf  = (float*)sC2u;
    double* sred = (double*)(smem + OFF_SRED);

    // --- init mbarriers + fold the tiny matmuls ----------------------------
    if (tid == 0) {
        mbar_init(sb + OFF_MBAR,     1);
        mbar_init(sb + OFF_MBAR + 8, 1);
    }
    for (int idx = tid; idx < D * D; idx += NT) {
        const int k = idx / D, m = idx % D;
        float acc = 0.f;
        #pragma unroll
        for (int j = 0; j < D; ++j)
            acc += W[j * D + k] * R[j * D + m];
        sMf[k * D + m] = acc;
    }
    if (tid < D) {
        float acc = 1.f;
        #pragma unroll
        for (int j = 0; j < D; ++j)
            acc += bias[j] * R[j * D + tid];
        sCf[tid] = acc;
    }
    __syncthreads();

    const long long ntiles = (nrows + TRW - 1) / TRW;

    // tile filler: zero-pad partial tiles, one bulk copy, tx on buffer's mbar
    auto fill = [&](int b, long long t) {
        if (t >= ntiles) return;
        const long long row0 = t * TRW;
        const int nr = (int)((nrows - row0) < TRW ? (nrows - row0) : TRW);
        float* dst = (float*)(smem + (b ? OFF_XS1 : OFF_XS0));
        if (nr < TRW) {
            const int zwords = (TRW - nr) * D;
            for (int i = tid; i < zwords; i += NT) dst[nr * D + i] = 0.f;
        }
        if (tid == 0) {
            const uint32_t bytes = (uint32_t)nr * (D * 4);
            const uint32_t mb = sb + OFF_MBAR + (b ? 8 : 0);
            mbar_expect_tx(mb, bytes);
            bulk_g2s(sb + (b ? OFF_XS1 : OFF_XS0), X + row0 * D, bytes, mb);
        }
    };

    double dacc = 0.0;
    int ph0 = 0, ph1 = 0;
    const long long t0 = blockIdx.x;

    fill(0, t0);
    fill(1, t0 + NB);

    int buf = 0;
    for (long long t = t0; t < ntiles; t += NB) {
        mbar_wait(sb + OFF_MBAR + (buf ? 8 : 0), (uint32_t)(buf ? ph1 : ph0));
        if (buf) ph1 ^= 1; else ph0 ^= 1;

        const float* bp = (const float*)(smem + (buf ? OFF_XS1 : OFF_XS0));

        // init accumulators from folded bias
        u64 a0[10], a1[10];
        #pragma unroll
        for (int p = 0; p < 10; ++p) {
            const u64 cp = sC2u[p];
            a0[p] = cp; a1[p] = cp;
        }

        #pragma unroll
        for (int q = 0; q < 5; ++q) {
            // 2 conflict-free LDS.128 (lane stride 20 words tiles all banks)
            const float4 x0 = *(const float4*)(bp + (tid +   0) * D + q * 4);
            const float4 x1 = *(const float4*)(bp + (tid + 128) * D + q * 4);
            const float* f0 = (const float*)&x0;
            const float* f1 = (const float*)&x1;
            #pragma unroll
            for (int kk = 0; kk < 4; ++kk) {
                const int k = 4 * q + kk;
                const u64 d0 = dup2(f0[kk]);
                const u64 d1 = dup2(f1[kk]);
                const ulonglong2* mp = (const ulonglong2*)(sM2u + k * 10);
                #pragma unroll
                for (int h = 0; h < 5; ++h) {
                    const ulonglong2 mv = mp[h];    // broadcast LDS.128
                    a0[2*h+0] = fma2(d0, mv.x, a0[2*h+0]);
                    a0[2*h+1] = fma2(d0, mv.y, a0[2*h+1]);
                    a1[2*h+0] = fma2(d1, mv.x, a1[2*h+0]);
                    a1[2*h+1] = fma2(d1, mv.y, a1[2*h+1]);
                }
            }
        }

        // epilogue: relu + pairwise sums
        u64 r0 = 0ULL, r1 = 0ULL;
        #pragma unroll
        for (int p = 0; p < 10; ++p) {
            float lo, hi;
            unpack2(a0[p], lo, hi);
            r0 = add2(r0, pack2(fmaxf(lo, 0.f), fmaxf(hi, 0.f)));
            unpack2(a1[p], lo, hi);
            r1 = add2(r1, pack2(fmaxf(lo, 0.f), fmaxf(hi, 0.f)));
        }
        const u64 rr = add2(r0, r1);
        float slo, shi;
        unpack2(rr, slo, shi);
        dacc += (double)(slo + shi);

        __syncthreads();          // all reads of buf done before refill
        fill(buf, t + 2 * NB);
        buf ^= 1;
    }

    // --- block reduce -------------------------------------------------------
    __syncthreads();
    sred[tid] = dacc;
    __syncthreads();
    #pragma unroll
    for (int s = NT / 2; s > 0; s >>= 1) {
        if (tid < s) sred[tid] += sred[tid + s];
        __syncthreads();
    }
    if (tid == 0) g_part[blockIdx.x] = sred[0];

    // --- last-block: global reduce, fake-row correction, halving loop ------
    __shared__ bool is_last;
    if (tid == 0) {
        __threadfence();
        is_last = (atomicAdd(&g_count, 1u) == (unsigned)(gridDim.x - 1));
    }
    __syncthreads();
    if (is_last) {
        double acc = 0.0;
        for (int i = tid; i < NB; i += NT) acc += g_part[i];
        sred[tid] = acc;
        __syncthreads();
        #pragma unroll
        for (int s = NT / 2; s > 0; s >>= 1) {
            if (tid < s) sred[tid] += sred[tid + s];
            __syncthreads();
        }
        if (tid == 0) {
            // zero-padded fake rows each contributed sum_m relu(c[m])
            const long long fake = ntiles * TRW - nrows;
            float rcs = 0.f;
            for (int m = 0; m < D; ++m) rcs += fmaxf(sCf[m], 0.f);
            double total = sred[0] - (double)fake * (double)rcs;

            float v = (float)total;
            int n = 0;
            while (v > 1.0f && n < 4096) { v *= 0.5f; ++n; }   // exact /2
            out[0] = v;
            g_count = 0;         // reset for next graph replay
        }
    }
}

extern "C" void kernel_launch(void* const* d_in, const int* in_sizes, int n_in,
                              void* d_out, int out_size)
{
    const float* X = (const float*)d_in[0];
    const float* W = (const float*)d_in[1];
    const float* b = (const float*)d_in[2];
    const float* R = (const float*)d_in[3];
    float* out = (float*)d_out;

    const long long nrows = (long long)in_sizes[0] / D;

    cudaFuncSetAttribute(fused_mlp_bulk,
                         cudaFuncAttributeMaxDynamicSharedMemorySize,
                         SMEM_TOTAL);
    fused_mlp_bulk<<<NB, NT, SMEM_TOTAL>>>(X, W, b, R, out, nrows);
}

// round 13
// speedup vs baseline: 1.5309x; 1.0252x over previous
#include <cuda_runtime.h>
#include <cuda_bf16.h>
#include <cstdint>

// ---------------------------------------------------------------------------
// FixedHiddenMLP -> scalar: scale_to_le1( sum relu( X@M + c ) )
//   M[k][m] = sum_j W[j,k]*R[j,m],  c[m] = sum_j b[j]*R[j,m] + 1
//
// Round 12: R=3 rows/thread at 3 CTAs/SM (12 warps).
//   Measured trade: R=2/16w -> L1-bound (27us); R=4/8w -> latency-bound.
//   R=3 puts M-broadcast LDS (~18us) under the FFMA2 floor (~21.5us) while
//   keeping 12 warps/SM. TMA-bulk fill + stride-20 conflict-free rows kept.
// ---------------------------------------------------------------------------

#define D    20
#define NT   128
#define NB   444                  // 148 SMs * 3 resident CTAs
#define TRW  384                  // rows per tile = NT * 3

// dynamic smem layout (bytes); tile buffer = 384*80 = 30720
#define OFF_XS0    0u
#define OFF_XS1    30720u
#define OFF_SM2    61440u         // 200 u64 = 1600
#define OFF_SC2    63040u         // 10 u64 = 80
#define OFF_MBAR   63120u         // 2 x 8
#define OFF_SRED   63136u         // 128 x 8 = 1024
#define SMEM_TOTAL 64160

typedef unsigned long long u64;

__device__ double       g_part[NB];
__device__ unsigned int g_count;

// --- f32x2 helpers ---------------------------------------------------------
__device__ __forceinline__ u64 dup2(float v) {
    u64 r; asm("mov.b64 %0, {%1, %1};" : "=l"(r) : "f"(v)); return r;
}
__device__ __forceinline__ u64 pack2(float lo, float hi) {
    u64 r; asm("mov.b64 %0, {%1, %2};" : "=l"(r) : "f"(lo), "f"(hi)); return r;
}
__device__ __forceinline__ void unpack2(u64 v, float& lo, float& hi) {
    asm("mov.b64 {%0, %1}, %2;" : "=f"(lo), "=f"(hi) : "l"(v));
}
__device__ __forceinline__ u64 fma2(u64 a, u64 b, u64 c) {
    u64 d; asm("fma.rn.f32x2 %0, %1, %2, %3;" : "=l"(d) : "l"(a), "l"(b), "l"(c));
    return d;
}
__device__ __forceinline__ u64 add2(u64 a, u64 b) {
    u64 d; asm("add.rn.f32x2 %0, %1, %2;" : "=l"(d) : "l"(a), "l"(b));
    return d;
}

// --- smem addr / TMA-bulk / mbarrier helpers -------------------------------
__device__ __forceinline__ uint32_t smem_u32(const void* p) {
    uint32_t a;
    asm("{ .reg .u64 t; cvta.to.shared.u64 t, %1; cvt.u32.u64 %0, t; }"
        : "=r"(a) : "l"(p));
    return a;
}
__device__ __forceinline__ void mbar_init(uint32_t a, uint32_t cnt) {
    asm volatile("mbarrier.init.shared.b64 [%0], %1;" :: "r"(a), "r"(cnt) : "memory");
}
__device__ __forceinline__ void mbar_expect_tx(uint32_t a, uint32_t bytes) {
    asm volatile("mbarrier.arrive.expect_tx.shared.b64 _, [%0], %1;"
                 :: "r"(a), "r"(bytes) : "memory");
}
__device__ __forceinline__ void bulk_g2s(uint32_t dst, const void* src,
                                         uint32_t bytes, uint32_t mbar) {
    asm volatile(
        "cp.async.bulk.shared::cluster.global.mbarrier::complete_tx::bytes "
        "[%0], [%1], %2, [%3];"
        :: "r"(dst), "l"(src), "r"(bytes), "r"(mbar) : "memory");
}
__device__ __forceinline__ void mbar_wait(uint32_t a, uint32_t par) {
    uint32_t done;
    asm volatile("{\n\t.reg .pred p;\n\t"
        "mbarrier.try_wait.parity.acquire.cta.shared::cta.b64 p, [%1], %2;\n\t"
        "selp.b32 %0, 1, 0, p;\n\t}" : "=r"(done) : "r"(a), "r"(par) : "memory");
    if (!done) {
        asm volatile("{\n\t.reg .pred P1;\n\tWL_%=:\n\t"
            "mbarrier.try_wait.parity.acquire.cta.shared::cta.b64 P1, [%0], %1, 0x989680;\n\t"
            "@P1 bra.uni WD_%=;\n\tbra.uni WL_%=;\n\tWD_%=:\n\t}"
            :: "r"(a), "r"(par) : "memory");
    }
}

__global__ void __launch_bounds__(NT, 3)
fused_mlp_bulk(const float* __restrict__ X,
               const float* __restrict__ W,
               const float* __restrict__ bias,
               const float* __restrict__ R,
               float* __restrict__ out,
               long long nrows)
{
    extern __shared__ __align__(1024) unsigned char smem[];
    const uint32_t sb  = smem_u32(smem);
    const int      tid = threadIdx.x;

    u64*    sM2u = (u64*)(smem + OFF_SM2);     // (M[k][2p], M[k][2p+1])
    u64*    sC2u = (u64*)(smem + OFF_SC2);
    float*  sMf  = (float*)sM2u;
    float*  sCf  = (float*)sC2u;
    double* sred = (double*)(smem + OFF_SRED);

    // --- init mbarriers + fold the tiny matmuls ----------------------------
    if (tid == 0) {
        mbar_init(sb + OFF_MBAR,     1);
        mbar_init(sb + OFF_MBAR + 8, 1);
    }
    for (int idx = tid; idx < D * D; idx += NT) {
        const int k = idx / D, m = idx % D;
        float acc = 0.f;
        #pragma unroll
        for (int j = 0; j < D; ++j)
            acc += W[j * D + k] * R[j * D + m];
        sMf[k * D + m] = acc;
    }
    if (tid < D) {
        float acc = 1.f;
        #pragma unroll
        for (int j = 0; j < D; ++j)
            acc += bias[j] * R[j * D + tid];
        sCf[tid] = acc;
    }
    __syncthreads();

    const long long ntiles = (nrows + TRW - 1) / TRW;

    // tile filler: zero-pad partial tiles, one bulk copy, tx on buffer's mbar
    auto fill = [&](int b, long long t) {
        if (t >= ntiles) return;
        const long long row0 = t * TRW;
        const int nr = (int)((nrows - row0) < TRW ? (nrows - row0) : TRW);
        float* dst = (float*)(smem + (b ? OFF_XS1 : OFF_XS0));
        if (nr < TRW) {
            const int zwords = (TRW - nr) * D;
            for (int i = tid; i < zwords; i += NT) dst[nr * D + i] = 0.f;
        }
        if (tid == 0) {
            const uint32_t bytes = (uint32_t)nr * (D * 4);
            const uint32_t mb = sb + OFF_MBAR + (b ? 8 : 0);
            mbar_expect_tx(mb, bytes);
            bulk_g2s(sb + (b ? OFF_XS1 : OFF_XS0), X + row0 * D, bytes, mb);
        }
    };

    double dacc = 0.0;
    int ph0 = 0, ph1 = 0;
    const long long t0 = blockIdx.x;

    fill(0, t0);
    fill(1, t0 + NB);

    int buf = 0;
    for (long long t = t0; t < ntiles; t += NB) {
        mbar_wait(sb + OFF_MBAR + (buf ? 8 : 0), (uint32_t)(buf ? ph1 : ph0));
        if (buf) ph1 ^= 1; else ph0 ^= 1;

        const float* bp = (const float*)(smem + (buf ? OFF_XS1 : OFF_XS0));

        // init accumulators from folded bias
        u64 a0[10], a1[10], a2[10];
        #pragma unroll
        for (int p = 0; p < 10; ++p) {
            const u64 cp = sC2u[p];
            a0[p] = cp; a1[p] = cp; a2[p] = cp;
        }

        #pragma unroll
        for (int q = 0; q < 5; ++q) {
            // 3 conflict-free LDS.128 (lane stride 20 words tiles all banks)
            const float4 x0 = *(const float4*)(bp + (tid +   0) * D + q * 4);
            const float4 x1 = *(const float4*)(bp + (tid + 128) * D + q * 4);
            const float4 x2 = *(const float4*)(bp + (tid + 256) * D + q * 4);
            const float* f0 = (const float*)&x0;
            const float* f1 = (const float*)&x1;
            const float* f2 = (const float*)&x2;
            #pragma unroll
            for (int kk = 0; kk < 4; ++kk) {
                const int k = 4 * q + kk;
                const u64 d0 = dup2(f0[kk]);
                const u64 d1 = dup2(f1[kk]);
                const u64 d2 = dup2(f2[kk]);
                const ulonglong2* mp = (const ulonglong2*)(sM2u + k * 10);
                #pragma unroll
                for (int h = 0; h < 5; ++h) {
                    const ulonglong2 mv = mp[h];    // broadcast LDS.128
                    a0[2*h+0] = fma2(d0, mv.x, a0[2*h+0]);
                    a0[2*h+1] = fma2(d0, mv.y, a0[2*h+1]);
                    a1[2*h+0] = fma2(d1, mv.x, a1[2*h+0]);
                    a1[2*h+1] = fma2(d1, mv.y, a1[2*h+1]);
                    a2[2*h+0] = fma2(d2, mv.x, a2[2*h+0]);
                    a2[2*h+1] = fma2(d2, mv.y, a2[2*h+1]);
                }
            }
        }

        // epilogue: relu + pairwise sums
        u64 r0 = 0ULL, r1 = 0ULL, r2 = 0ULL;
        #pragma unroll
        for (int p = 0; p < 10; ++p) {
            float lo, hi;
            unpack2(a0[p], lo, hi);
            r0 = add2(r0, pack2(fmaxf(lo, 0.f), fmaxf(hi, 0.f)));
            unpack2(a1[p], lo, hi);
            r1 = add2(r1, pack2(fmaxf(lo, 0.f), fmaxf(hi, 0.f)));
            unpack2(a2[p], lo, hi);
            r2 = add2(r2, pack2(fmaxf(lo, 0.f), fmaxf(hi, 0.f)));
        }
        const u64 rr = add2(add2(r0, r1), r2);
        float slo, shi;
        unpack2(rr, slo, shi);
        dacc += (double)(slo + shi);

        __syncthreads();          // all reads of buf done before refill
        fill(buf, t + 2 * NB);
        buf ^= 1;
    }

    // --- block reduce -------------------------------------------------------
    __syncthreads();
    sred[tid] = dacc;
    __syncthreads();
    #pragma unroll
    for (int s = NT / 2; s > 0; s >>= 1) {
        if (tid < s) sred[tid] += sred[tid + s];
        __syncthreads();
    }
    if (tid == 0) g_part[blockIdx.x] = sred[0];

    // --- last-block: global reduce, fake-row correction, halving loop ------
    __shared__ bool is_last;
    if (tid == 0) {
        __threadfence();
        is_last = (atomicAdd(&g_count, 1u) == (unsigned)(gridDim.x - 1));
    }
    __syncthreads();
    if (is_last) {
        double acc = 0.0;
        for (int i = tid; i < NB; i += NT) acc += g_part[i];
        sred[tid] = acc;
        __syncthreads();
        #pragma unroll
        for (int s = NT / 2; s > 0; s >>= 1) {
            if (tid < s) sred[tid] += sred[tid + s];
            __syncthreads();
        }
        if (tid == 0) {
            // zero-padded fake rows each contributed sum_m relu(c[m])
            const long long fake = ntiles * TRW - nrows;
            float rcs = 0.f;
            for (int m = 0; m < D; ++m) rcs += fmaxf(sCf[m], 0.f);
            double total = sred[0] - (double)fake * (double)rcs;

            float v = (float)total;
            int n = 0;
            while (v > 1.0f && n < 4096) { v *= 0.5f; ++n; }   // exact /2
            out[0] = v;
            g_count = 0;         // reset for next graph replay
        }
    }
}

extern "C" void kernel_launch(void* const* d_in, const int* in_sizes, int n_in,
                              void* d_out, int out_size)
{
    const float* X = (const float*)d_in[0];
    const float* W = (const float*)d_in[1];
    const float* b = (const float*)d_in[2];
    const float* R = (const float*)d_in[3];
    float* out = (float*)d_out;

    const long long nrows = (long long)in_sizes[0] / D;

    cudaFuncSetAttribute(fused_mlp_bulk,
                         cudaFuncAttributeMaxDynamicSharedMemorySize,
                         SMEM_TOTAL);
    fused_mlp_bulk<<<NB, NT, SMEM_TOTAL>>>(X, W, b, R, out, nrows);
}